// round 1
// baseline (speedup 1.0000x reference)
#include <cuda_runtime.h>

typedef unsigned long long u64;

#define NRAYS 32768
#define THREADS 128

// ---- packed f32x2 helpers (Blackwell sm_103a) ----
__device__ __forceinline__ u64 pack2(float a, float b) {
    u64 r; asm("mov.b64 %0, {%1, %2};" : "=l"(r) : "f"(a), "f"(b)); return r;
}
__device__ __forceinline__ float2 unpack2(u64 v) {
    float2 r; asm("mov.b64 {%0, %1}, %2;" : "=f"(r.x), "=f"(r.y) : "l"(v)); return r;
}
__device__ __forceinline__ u64 ffma2(u64 a, u64 b, u64 c) {
    u64 d; asm("fma.rn.f32x2 %0, %1, %2, %3;" : "=l"(d) : "l"(a), "l"(b), "l"(c)); return d;
}
__device__ __forceinline__ u64 fadd2(u64 a, u64 b) {
    u64 d; asm("add.rn.f32x2 %0, %1, %2;" : "=l"(d) : "l"(a), "l"(b)); return d;
}
__device__ __forceinline__ u64 relu2(u64 v) {
    float2 f = unpack2(v);
    return pack2(fmaxf(f.x, 0.0f), fmaxf(f.y, 0.0f));
}

struct __align__(16) Weights {
    float W0[3 * 64];
    float b0[64];
    float W1[64 * 64];
    float b1[64];
    float W2[64];
    float b2;
    float pad[3];
    float Wr0[6 * 64];
    float br0[64];
    float Wr1[64 * 3];
    float br1[3];
};

// SDF MLP: relu(relu(p@W0+b0)@W1+b1)@W2+b2 — fp32, f32x2 over neuron pairs.
__device__ __forceinline__ float sdf_eval(const Weights& s, float px, float py, float pz) {
    u64 h0[32];
    {
        const u64* bp = (const u64*)s.b0;
        #pragma unroll
        for (int j = 0; j < 32; j++) h0[j] = bp[j];
        float p[3] = {px, py, pz};
        #pragma unroll
        for (int i = 0; i < 3; i++) {
            u64 xi = pack2(p[i], p[i]);
            const u64* w = (const u64*)(s.W0 + i * 64);
            #pragma unroll
            for (int j = 0; j < 32; j++) h0[j] = ffma2(xi, w[j], h0[j]);
        }
        #pragma unroll
        for (int j = 0; j < 32; j++) h0[j] = relu2(h0[j]);
    }
    u64 h1[32];
    {
        const u64* bp = (const u64*)s.b1;
        #pragma unroll
        for (int j = 0; j < 32; j++) h1[j] = bp[j];
        #pragma unroll 4
        for (int k = 0; k < 64; k++) {
            float2 pr = unpack2(h0[k >> 1]);
            float hk = (k & 1) ? pr.y : pr.x;
            u64 xk = pack2(hk, hk);
            const u64* w = (const u64*)(s.W1 + k * 64);
            #pragma unroll
            for (int j = 0; j < 32; j++) h1[j] = ffma2(xk, w[j], h1[j]);
        }
    }
    // layer 2 with relu fused into the reduction
    const u64* w2 = (const u64*)s.W2;
    u64 a0 = 0ull, a1 = 0ull, a2 = 0ull, a3 = 0ull;
    #pragma unroll
    for (int j = 0; j < 32; j += 4) {
        a0 = ffma2(relu2(h1[j + 0]), w2[j + 0], a0);
        a1 = ffma2(relu2(h1[j + 1]), w2[j + 1], a1);
        a2 = ffma2(relu2(h1[j + 2]), w2[j + 2], a2);
        a3 = ffma2(relu2(h1[j + 3]), w2[j + 3], a3);
    }
    float2 f = unpack2(fadd2(fadd2(a0, a1), fadd2(a2, a3)));
    return f.x + f.y + s.b2;
}

// Reflectance MLP: sigmoid(relu([p,d]@Wr0+br0)@Wr1+br1)
__device__ __forceinline__ void refl_eval(const Weights& s, const float* in6, float* rgb) {
    u64 h[32];
    const u64* bp = (const u64*)s.br0;
    #pragma unroll
    for (int j = 0; j < 32; j++) h[j] = bp[j];
    #pragma unroll
    for (int i = 0; i < 6; i++) {
        u64 xi = pack2(in6[i], in6[i]);
        const u64* w = (const u64*)(s.Wr0 + i * 64);
        #pragma unroll
        for (int j = 0; j < 32; j++) h[j] = ffma2(xi, w[j], h[j]);
    }
    float acc0 = s.br1[0], acc1 = s.br1[1], acc2 = s.br1[2];
    #pragma unroll 8
    for (int k = 0; k < 64; k++) {
        float2 pr = unpack2(h[k >> 1]);
        float hk = fmaxf((k & 1) ? pr.y : pr.x, 0.0f);
        acc0 = fmaf(hk, s.Wr1[k * 3 + 0], acc0);
        acc1 = fmaf(hk, s.Wr1[k * 3 + 1], acc1);
        acc2 = fmaf(hk, s.Wr1[k * 3 + 2], acc2);
    }
    rgb[0] = 1.0f / (1.0f + expf(-acc0));
    rgb[1] = 1.0f / (1.0f + expf(-acc1));
    rgb[2] = 1.0f / (1.0f + expf(-acc2));
}

__global__ void __launch_bounds__(THREADS) sdf_march_kernel(
    const float* __restrict__ rays,
    const float* __restrict__ gW0, const float* __restrict__ gb0,
    const float* __restrict__ gW1, const float* __restrict__ gb1,
    const float* __restrict__ gW2, const float* __restrict__ gb2,
    const float* __restrict__ gWr0, const float* __restrict__ gbr0,
    const float* __restrict__ gWr1, const float* __restrict__ gbr1,
    float* __restrict__ out)
{
    __shared__ Weights s;
    int tid = threadIdx.x;
    for (int i = tid; i < 3 * 64; i += THREADS) s.W0[i] = gW0[i];
    for (int i = tid; i < 64; i += THREADS) s.b0[i] = gb0[i];
    for (int i = tid; i < 64 * 64; i += THREADS) s.W1[i] = gW1[i];
    for (int i = tid; i < 64; i += THREADS) s.b1[i] = gb1[i];
    for (int i = tid; i < 64; i += THREADS) s.W2[i] = gW2[i];
    if (tid == 0) s.b2 = gb2[0];
    for (int i = tid; i < 6 * 64; i += THREADS) s.Wr0[i] = gWr0[i];
    for (int i = tid; i < 64; i += THREADS) s.br0[i] = gbr0[i];
    for (int i = tid; i < 64 * 3; i += THREADS) s.Wr1[i] = gWr1[i];
    for (int i = tid; i < 3; i += THREADS) s.br1[i] = gbr1[i];
    __syncthreads();

    int ray = blockIdx.x * THREADS + tid;
    const float* r = rays + ray * 6;
    float rox = r[0], roy = r[1], roz = r[2];
    float rdx = r[3], rdy = r[4], rdz = r[5];

    // ---- sphere march (hit lanes freeze cd -> all-hit break is exact) ----
    float cd = 0.0f;
    bool hit = false;
    #pragma unroll 1
    for (int it = 0; it < 64; ++it) {
        float d = sdf_eval(s, fmaf(rdx, cd, rox), fmaf(rdy, cd, roy), fmaf(rdz, cd, roz));
        bool h = (d < 1e-4f) && (cd >= 0.0f) && (cd <= 1.0f);
        hit = hit || h;
        if (!hit) cd += d;
        if (__all_sync(0xffffffffu, hit)) break;
    }

    // ---- reflectance ----
    float rgb[3];
    {
        float in6[6] = { fmaf(rdx, cd, rox), fmaf(rdy, cd, roy), fmaf(rdz, cd, roz),
                         rdx, rdy, rdz };
        refl_eval(s, in6, rgb);
        if (!hit) { rgb[0] = 0.0f; rgb[1] = 0.0f; rgb[2] = 0.0f; }
    }

    // ---- throughput argmin scan: t = step*i, i = 0..64 (i=0 is the init sample) ----
    const float step = (1.0f + 1.0f / 64.0f) / 64.0f;  // 65/4096, exact
    float cm = 0.0f;
    int idx = 0;
    #pragma unroll 1
    for (int i = 0; i <= 64; ++i) {
        float t = step * (float)i;
        float sd = sdf_eval(s, fmaf(rdx, t, rox), fmaf(rdy, t, roy), fmaf(rdz, t, roz));
        if (i == 0) cm = sd;
        else if (sd < cm) { cm = sd; idx = i; }   // strict <: ties keep earlier index
    }
    float tb = (float)idx * step;
    float tp = sdf_eval(s, fmaf(rdx, tb, rox), fmaf(rdy, tb, roy), fmaf(rdz, tb, roz));

    ((float4*)out)[ray] = make_float4(rgb[0], rgb[1], rgb[2], tp);
}

extern "C" void kernel_launch(void* const* d_in, const int* in_sizes, int n_in,
                              void* d_out, int out_size) {
    sdf_march_kernel<<<NRAYS / THREADS, THREADS>>>(
        (const float*)d_in[0],
        (const float*)d_in[1], (const float*)d_in[2],
        (const float*)d_in[3], (const float*)d_in[4],
        (const float*)d_in[5], (const float*)d_in[6],
        (const float*)d_in[7], (const float*)d_in[8],
        (const float*)d_in[9], (const float*)d_in[10],
        (float*)d_out);
}

// round 5
// speedup vs baseline: 1.9679x; 1.9679x over previous
#include <cuda_runtime.h>

typedef unsigned long long u64;

#define NRAYS 32768
#define THREADS 128

// ---- packed f32x2 helpers (Blackwell sm_103a) ----
__device__ __forceinline__ u64 pack2(float a, float b) {
    u64 r; asm("mov.b64 %0, {%1, %2};" : "=l"(r) : "f"(a), "f"(b)); return r;
}
__device__ __forceinline__ float2 unpack2(u64 v) {
    float2 r; asm("mov.b64 {%0, %1}, %2;" : "=f"(r.x), "=f"(r.y) : "l"(v)); return r;
}
__device__ __forceinline__ u64 ffma2(u64 a, u64 b, u64 c) {
    u64 d; asm("fma.rn.f32x2 %0, %1, %2, %3;" : "=l"(d) : "l"(a), "l"(b), "l"(c)); return d;
}
__device__ __forceinline__ u64 fadd2(u64 a, u64 b) {
    u64 d; asm("add.rn.f32x2 %0, %1, %2;" : "=l"(d) : "l"(a), "l"(b)); return d;
}
__device__ __forceinline__ u64 relu2(u64 v) {
    float2 f = unpack2(v);
    return pack2(fmaxf(f.x, 0.0f), fmaxf(f.y, 0.0f));
}
__device__ __forceinline__ u64 splat2(float x) { return pack2(x, x); }

struct __align__(16) Weights {
    float W0[3 * 64];
    float b0[64];
    float W1[64 * 64];
    float b1[64];
    float W2[64];
    float b2;
    float pad[3];
    float Wr0[6 * 64];
    float br0[64];
    float Wr1[64 * 3];
    float br1[3];
};

// SDF MLP: relu(relu(p@W0+b0)@W1+b1)@W2+b2 — exact fp32, f32x2 neuron pairs,
// float4 weight loads, static register indexing, layer1 half-tiled with
// layer2 fused. __noinline__ is load-bearing: it stops nvcc from hoisting
// the (loop-invariant) shared-memory weight loads out of the march/scan
// loops, which previously exploded the live set and spilled ~10KB/thread.
__device__ __noinline__ float sdf_eval(const Weights* __restrict__ sp,
                                       float px, float py, float pz) {
    const Weights& s = *sp;
    u64 h0[32];
    {
        const float4* b4 = (const float4*)s.b0;
        #pragma unroll
        for (int q = 0; q < 16; q++) {
            float4 v = b4[q];
            h0[2 * q]     = pack2(v.x, v.y);
            h0[2 * q + 1] = pack2(v.z, v.w);
        }
        float p[3] = {px, py, pz};
        #pragma unroll
        for (int i = 0; i < 3; i++) {
            u64 xi = splat2(p[i]);
            const float4* w = (const float4*)(s.W0 + i * 64);
            #pragma unroll
            for (int q = 0; q < 16; q++) {
                float4 wv = w[q];
                h0[2 * q]     = ffma2(xi, pack2(wv.x, wv.y), h0[2 * q]);
                h0[2 * q + 1] = ffma2(xi, pack2(wv.z, wv.w), h0[2 * q + 1]);
            }
        }
        #pragma unroll
        for (int q = 0; q < 32; q++) h0[q] = relu2(h0[q]);
    }

    u64 d0 = 0ull, d1 = 0ull, d2 = 0ull, d3 = 0ull;
    #pragma unroll
    for (int half = 0; half < 2; half++) {
        u64 acc[16];
        {
            const float4* b4 = (const float4*)(s.b1 + half * 32);
            #pragma unroll
            for (int q = 0; q < 8; q++) {
                float4 v = b4[q];
                acc[2 * q]     = pack2(v.x, v.y);
                acc[2 * q + 1] = pack2(v.z, v.w);
            }
        }
        #pragma unroll
        for (int kk = 0; kk < 32; kk++) {
            float2 hp = unpack2(h0[kk]);
            {
                u64 x = splat2(hp.x);
                const float4* w = (const float4*)(s.W1 + (2 * kk) * 64 + half * 32);
                #pragma unroll
                for (int q = 0; q < 8; q++) {
                    float4 wv = w[q];
                    acc[2 * q]     = ffma2(x, pack2(wv.x, wv.y), acc[2 * q]);
                    acc[2 * q + 1] = ffma2(x, pack2(wv.z, wv.w), acc[2 * q + 1]);
                }
            }
            {
                u64 x = splat2(hp.y);
                const float4* w = (const float4*)(s.W1 + (2 * kk + 1) * 64 + half * 32);
                #pragma unroll
                for (int q = 0; q < 8; q++) {
                    float4 wv = w[q];
                    acc[2 * q]     = ffma2(x, pack2(wv.x, wv.y), acc[2 * q]);
                    acc[2 * q + 1] = ffma2(x, pack2(wv.z, wv.w), acc[2 * q + 1]);
                }
            }
        }
        // layer 2 (fused): relu then dot with W2 half
        const float4* w2 = (const float4*)(s.W2 + half * 32);
        #pragma unroll
        for (int q = 0; q < 8; q += 2) {
            float4 a = w2[q], b = w2[q + 1];
            d0 = ffma2(relu2(acc[2 * q]),     pack2(a.x, a.y), d0);
            d1 = ffma2(relu2(acc[2 * q + 1]), pack2(a.z, a.w), d1);
            d2 = ffma2(relu2(acc[2 * q + 2]), pack2(b.x, b.y), d2);
            d3 = ffma2(relu2(acc[2 * q + 3]), pack2(b.z, b.w), d3);
        }
    }
    float2 f = unpack2(fadd2(fadd2(d0, d1), fadd2(d2, d3)));
    return f.x + f.y + s.b2;
}

// Reflectance MLP: sigmoid(relu([p,d]@Wr0+br0)@Wr1+br1). Called once,
// outside all loops; __noinline__ keeps its live set out of the kernel frame.
__device__ __noinline__ void refl_eval(const Weights* __restrict__ sp,
                                       const float* in6, float* rgb) {
    const Weights& s = *sp;
    u64 h[32];
    {
        const float4* b4 = (const float4*)s.br0;
        #pragma unroll
        for (int q = 0; q < 16; q++) {
            float4 v = b4[q];
            h[2 * q]     = pack2(v.x, v.y);
            h[2 * q + 1] = pack2(v.z, v.w);
        }
        #pragma unroll
        for (int i = 0; i < 6; i++) {
            u64 xi = splat2(in6[i]);
            const float4* w = (const float4*)(s.Wr0 + i * 64);
            #pragma unroll
            for (int q = 0; q < 16; q++) {
                float4 wv = w[q];
                h[2 * q]     = ffma2(xi, pack2(wv.x, wv.y), h[2 * q]);
                h[2 * q + 1] = ffma2(xi, pack2(wv.z, wv.w), h[2 * q + 1]);
            }
        }
    }
    float a0 = s.br1[0], a1 = s.br1[1], a2 = s.br1[2];
    #pragma unroll
    for (int kk = 0; kk < 32; kk++) {
        float2 hp = unpack2(h[kk]);
        float v0 = fmaxf(hp.x, 0.0f);
        float v1 = fmaxf(hp.y, 0.0f);
        const float* w = s.Wr1 + (2 * kk) * 3;
        a0 = fmaf(v0, w[0], a0);
        a1 = fmaf(v0, w[1], a1);
        a2 = fmaf(v0, w[2], a2);
        a0 = fmaf(v1, w[3], a0);
        a1 = fmaf(v1, w[4], a1);
        a2 = fmaf(v1, w[5], a2);
    }
    rgb[0] = 1.0f / (1.0f + expf(-a0));
    rgb[1] = 1.0f / (1.0f + expf(-a1));
    rgb[2] = 1.0f / (1.0f + expf(-a2));
}

__global__ void __launch_bounds__(THREADS) sdf_march_kernel(
    const float* __restrict__ rays,
    const float* __restrict__ gW0, const float* __restrict__ gb0,
    const float* __restrict__ gW1, const float* __restrict__ gb1,
    const float* __restrict__ gW2, const float* __restrict__ gb2,
    const float* __restrict__ gWr0, const float* __restrict__ gbr0,
    const float* __restrict__ gWr1, const float* __restrict__ gbr1,
    float* __restrict__ out)
{
    __shared__ Weights s;
    int tid = threadIdx.x;
    for (int i = tid; i < 3 * 64; i += THREADS) s.W0[i] = gW0[i];
    for (int i = tid; i < 64; i += THREADS) s.b0[i] = gb0[i];
    for (int i = tid; i < 64 * 64; i += THREADS) s.W1[i] = gW1[i];
    for (int i = tid; i < 64; i += THREADS) s.b1[i] = gb1[i];
    for (int i = tid; i < 64; i += THREADS) s.W2[i] = gW2[i];
    if (tid == 0) s.b2 = gb2[0];
    for (int i = tid; i < 6 * 64; i += THREADS) s.Wr0[i] = gWr0[i];
    for (int i = tid; i < 64; i += THREADS) s.br0[i] = gbr0[i];
    for (int i = tid; i < 64 * 3; i += THREADS) s.Wr1[i] = gWr1[i];
    for (int i = tid; i < 3; i += THREADS) s.br1[i] = gbr1[i];
    __syncthreads();

    int ray = blockIdx.x * THREADS + tid;
    const float* r = rays + ray * 6;
    float rox = r[0], roy = r[1], roz = r[2];
    float rdx = r[3], rdy = r[4], rdz = r[5];

    // ---- sphere march (hit lanes freeze cd -> all-hit break is exact) ----
    float cd = 0.0f;
    bool hit = false;
    #pragma unroll 1
    for (int it = 0; it < 64; ++it) {
        asm volatile("" ::: "memory");   // block cross-iteration hoist/CSE
        float d = sdf_eval(&s, fmaf(rdx, cd, rox), fmaf(rdy, cd, roy), fmaf(rdz, cd, roz));
        bool h = (d < 1e-4f) && (cd >= 0.0f) && (cd <= 1.0f);
        hit = hit || h;
        if (!hit) cd += d;
        if (__all_sync(0xffffffffu, hit)) break;
    }

    // ---- reflectance ----
    float rgb[3];
    {
        float in6[6] = { fmaf(rdx, cd, rox), fmaf(rdy, cd, roy), fmaf(rdz, cd, roz),
                         rdx, rdy, rdz };
        refl_eval(&s, in6, rgb);
        if (!hit) { rgb[0] = 0.0f; rgb[1] = 0.0f; rgb[2] = 0.0f; }
    }

    // ---- throughput argmin scan: t = step*i, i = 0..64 ----
    // tput = sdf(best_pos) is bit-identical to the scan's running min cm
    // (same weight values, identical position arithmetic), so the final
    // eval is eliminated and only the min value is tracked.
    const float step = (1.0f + 1.0f / 64.0f) / 64.0f;  // 65/4096, exact fp32
    float cm = sdf_eval(&s, rox, roy, roz);
    #pragma unroll 1
    for (int i = 1; i <= 64; ++i) {
        asm volatile("" ::: "memory");   // block cross-iteration hoist/CSE
        float t = step * (float)i;
        float sd = sdf_eval(&s, fmaf(rdx, t, rox), fmaf(rdy, t, roy), fmaf(rdz, t, roz));
        cm = fminf(cm, sd);
    }
    float tp = cm;

    ((float4*)out)[ray] = make_float4(rgb[0], rgb[1], rgb[2], tp);
}

extern "C" void kernel_launch(void* const* d_in, const int* in_sizes, int n_in,
                              void* d_out, int out_size) {
    sdf_march_kernel<<<NRAYS / THREADS, THREADS>>>(
        (const float*)d_in[0],
        (const float*)d_in[1], (const float*)d_in[2],
        (const float*)d_in[3], (const float*)d_in[4],
        (const float*)d_in[5], (const float*)d_in[6],
        (const float*)d_in[7], (const float*)d_in[8],
        (const float*)d_in[9], (const float*)d_in[10],
        (float*)d_out);
}

// round 7
// speedup vs baseline: 2.0730x; 1.0535x over previous
#include <cuda_runtime.h>

typedef unsigned long long u64;

#define NRAYS 32768
#define THREADS 128
#define NBLK (NRAYS / THREADS)   // 256 ray-blocks; grid = 2*NBLK (march | scan)

// ---- packed f32x2 helpers (Blackwell sm_103a) ----
__device__ __forceinline__ u64 pack2(float a, float b) {
    u64 r; asm("mov.b64 %0, {%1, %2};" : "=l"(r) : "f"(a), "f"(b)); return r;
}
__device__ __forceinline__ float2 unpack2(u64 v) {
    float2 r; asm("mov.b64 {%0, %1}, %2;" : "=f"(r.x), "=f"(r.y) : "l"(v)); return r;
}
__device__ __forceinline__ u64 ffma2(u64 a, u64 b, u64 c) {
    u64 d; asm("fma.rn.f32x2 %0, %1, %2, %3;" : "=l"(d) : "l"(a), "l"(b), "l"(c)); return d;
}
__device__ __forceinline__ u64 fadd2(u64 a, u64 b) {
    u64 d; asm("add.rn.f32x2 %0, %1, %2;" : "=l"(d) : "l"(a), "l"(b)); return d;
}
__device__ __forceinline__ u64 relu2(u64 v) {
    float2 f = unpack2(v);
    return pack2(fmaxf(f.x, 0.0f), fmaxf(f.y, 0.0f));
}
__device__ __forceinline__ u64 splat2(float x) { return pack2(x, x); }

struct __align__(16) Weights {
    float W0[3 * 64];
    float b0[64];
    float W1[64 * 64];
    float b1[64];
    float W2[64];
    float b2;
    float pad[3];
    float Wr0[6 * 64];
    float br0[64];
    float Wr1[64 * 3];
    float br1[3];
};

// SDF MLP: relu(relu(p@W0+b0)@W1+b1)@W2+b2 — exact fp32, f32x2 neuron pairs,
// float4 weight loads, static register indexing, layer1 half-tiled with
// layer2 fused. __noinline__ is load-bearing: it stops nvcc from hoisting
// the loop-invariant shared-memory weight loads out of the march/scan loops
// (which previously spilled ~10KB/thread).
__device__ __noinline__ float sdf_eval(const Weights* __restrict__ sp,
                                       float px, float py, float pz) {
    const Weights& s = *sp;
    u64 h0[32];
    {
        const float4* b4 = (const float4*)s.b0;
        #pragma unroll
        for (int q = 0; q < 16; q++) {
            float4 v = b4[q];
            h0[2 * q]     = pack2(v.x, v.y);
            h0[2 * q + 1] = pack2(v.z, v.w);
        }
        float p[3] = {px, py, pz};
        #pragma unroll
        for (int i = 0; i < 3; i++) {
            u64 xi = splat2(p[i]);
            const float4* w = (const float4*)(s.W0 + i * 64);
            #pragma unroll
            for (int q = 0; q < 16; q++) {
                float4 wv = w[q];
                h0[2 * q]     = ffma2(xi, pack2(wv.x, wv.y), h0[2 * q]);
                h0[2 * q + 1] = ffma2(xi, pack2(wv.z, wv.w), h0[2 * q + 1]);
            }
        }
        #pragma unroll
        for (int q = 0; q < 32; q++) h0[q] = relu2(h0[q]);
    }

    u64 d0 = 0ull, d1 = 0ull, d2 = 0ull, d3 = 0ull;
    #pragma unroll
    for (int half = 0; half < 2; half++) {
        u64 acc[16];
        {
            const float4* b4 = (const float4*)(s.b1 + half * 32);
            #pragma unroll
            for (int q = 0; q < 8; q++) {
                float4 v = b4[q];
                acc[2 * q]     = pack2(v.x, v.y);
                acc[2 * q + 1] = pack2(v.z, v.w);
            }
        }
        #pragma unroll
        for (int kk = 0; kk < 32; kk++) {
            float2 hp = unpack2(h0[kk]);
            {
                u64 x = splat2(hp.x);
                const float4* w = (const float4*)(s.W1 + (2 * kk) * 64 + half * 32);
                #pragma unroll
                for (int q = 0; q < 8; q++) {
                    float4 wv = w[q];
                    acc[2 * q]     = ffma2(x, pack2(wv.x, wv.y), acc[2 * q]);
                    acc[2 * q + 1] = ffma2(x, pack2(wv.z, wv.w), acc[2 * q + 1]);
                }
            }
            {
                u64 x = splat2(hp.y);
                const float4* w = (const float4*)(s.W1 + (2 * kk + 1) * 64 + half * 32);
                #pragma unroll
                for (int q = 0; q < 8; q++) {
                    float4 wv = w[q];
                    acc[2 * q]     = ffma2(x, pack2(wv.x, wv.y), acc[2 * q]);
                    acc[2 * q + 1] = ffma2(x, pack2(wv.z, wv.w), acc[2 * q + 1]);
                }
            }
        }
        // layer 2 (fused): relu then dot with W2 half
        const float4* w2 = (const float4*)(s.W2 + half * 32);
        #pragma unroll
        for (int q = 0; q < 8; q += 2) {
            float4 a = w2[q], b = w2[q + 1];
            d0 = ffma2(relu2(acc[2 * q]),     pack2(a.x, a.y), d0);
            d1 = ffma2(relu2(acc[2 * q + 1]), pack2(a.z, a.w), d1);
            d2 = ffma2(relu2(acc[2 * q + 2]), pack2(b.x, b.y), d2);
            d3 = ffma2(relu2(acc[2 * q + 3]), pack2(b.z, b.w), d3);
        }
    }
    float2 f = unpack2(fadd2(fadd2(d0, d1), fadd2(d2, d3)));
    return f.x + f.y + s.b2;
}

// Reflectance MLP: sigmoid(relu([p,d]@Wr0+br0)@Wr1+br1). Called once, out of
// all loops; __noinline__ keeps its live set out of the kernel frame.
__device__ __noinline__ void refl_eval(const Weights* __restrict__ sp,
                                       const float* in6, float* rgb) {
    const Weights& s = *sp;
    u64 h[32];
    {
        const float4* b4 = (const float4*)s.br0;
        #pragma unroll
        for (int q = 0; q < 16; q++) {
            float4 v = b4[q];
            h[2 * q]     = pack2(v.x, v.y);
            h[2 * q + 1] = pack2(v.z, v.w);
        }
        #pragma unroll
        for (int i = 0; i < 6; i++) {
            u64 xi = splat2(in6[i]);
            const float4* w = (const float4*)(s.Wr0 + i * 64);
            #pragma unroll
            for (int q = 0; q < 16; q++) {
                float4 wv = w[q];
                h[2 * q]     = ffma2(xi, pack2(wv.x, wv.y), h[2 * q]);
                h[2 * q + 1] = ffma2(xi, pack2(wv.z, wv.w), h[2 * q + 1]);
            }
        }
    }
    float a0 = s.br1[0], a1 = s.br1[1], a2 = s.br1[2];
    #pragma unroll
    for (int kk = 0; kk < 32; kk++) {
        float2 hp = unpack2(h[kk]);
        float v0 = fmaxf(hp.x, 0.0f);
        float v1 = fmaxf(hp.y, 0.0f);
        const float* w = s.Wr1 + (2 * kk) * 3;
        a0 = fmaf(v0, w[0], a0);
        a1 = fmaf(v0, w[1], a1);
        a2 = fmaf(v0, w[2], a2);
        a0 = fmaf(v1, w[3], a0);
        a1 = fmaf(v1, w[4], a1);
        a2 = fmaf(v1, w[5], a2);
    }
    rgb[0] = 1.0f / (1.0f + expf(-a0));
    rgb[1] = 1.0f / (1.0f + expf(-a1));
    rgb[2] = 1.0f / (1.0f + expf(-a2));
}

// Grid = 2*NBLK. Blocks [0, NBLK): sphere-march + reflectance -> out[4r+0..2].
// Blocks [NBLK, 2*NBLK): throughput argmin scan -> out[4r+3]. The two tasks
// are independent (scan uses the same weight VALUES via stop_gradient), and
// they write disjoint components, so splitting doubles resident warps/SM.
__global__ void __launch_bounds__(THREADS, 3) sdf_march_kernel(
    const float* __restrict__ rays,
    const float* __restrict__ gW0, const float* __restrict__ gb0,
    const float* __restrict__ gW1, const float* __restrict__ gb1,
    const float* __restrict__ gW2, const float* __restrict__ gb2,
    const float* __restrict__ gWr0, const float* __restrict__ gbr0,
    const float* __restrict__ gWr1, const float* __restrict__ gbr1,
    float* __restrict__ out)
{
    __shared__ Weights s;
    int tid = threadIdx.x;
    for (int i = tid; i < 3 * 64; i += THREADS) s.W0[i] = gW0[i];
    for (int i = tid; i < 64; i += THREADS) s.b0[i] = gb0[i];
    for (int i = tid; i < 64 * 64; i += THREADS) s.W1[i] = gW1[i];
    for (int i = tid; i < 64; i += THREADS) s.b1[i] = gb1[i];
    for (int i = tid; i < 64; i += THREADS) s.W2[i] = gW2[i];
    if (tid == 0) s.b2 = gb2[0];
    for (int i = tid; i < 6 * 64; i += THREADS) s.Wr0[i] = gWr0[i];
    for (int i = tid; i < 64; i += THREADS) s.br0[i] = gbr0[i];
    for (int i = tid; i < 64 * 3; i += THREADS) s.Wr1[i] = gWr1[i];
    for (int i = tid; i < 3; i += THREADS) s.br1[i] = gbr1[i];
    __syncthreads();

    bool is_scan = blockIdx.x >= NBLK;
    int ray = (blockIdx.x - (is_scan ? NBLK : 0)) * THREADS + tid;
    const float* r = rays + ray * 6;
    float rox = r[0], roy = r[1], roz = r[2];
    float rdx = r[3], rdy = r[4], rdz = r[5];

    if (!is_scan) {
        // ---- sphere march (hit lanes freeze cd -> all-hit break is exact) ----
        float cd = 0.0f;
        bool hit = false;
        #pragma unroll 1
        for (int it = 0; it < 64; ++it) {
            asm volatile("" ::: "memory");   // block cross-iteration hoist/CSE
            float d = sdf_eval(&s, fmaf(rdx, cd, rox), fmaf(rdy, cd, roy), fmaf(rdz, cd, roz));
            bool h = (d < 1e-4f) && (cd >= 0.0f) && (cd <= 1.0f);
            hit = hit || h;
            if (!hit) cd += d;
            if (__all_sync(0xffffffffu, hit)) break;
        }

        // ---- reflectance (skipped entirely for all-miss warps) ----
        float rgb[3] = {0.0f, 0.0f, 0.0f};
        if (__any_sync(0xffffffffu, hit)) {
            float in6[6] = { fmaf(rdx, cd, rox), fmaf(rdy, cd, roy), fmaf(rdz, cd, roz),
                             rdx, rdy, rdz };
            refl_eval(&s, in6, rgb);
            if (!hit) { rgb[0] = 0.0f; rgb[1] = 0.0f; rgb[2] = 0.0f; }
        }
        out[4 * ray + 0] = rgb[0];
        out[4 * ray + 1] = rgb[1];
        out[4 * ray + 2] = rgb[2];
    } else {
        // ---- throughput argmin scan: t = step*i, i = 0..64 ----
        // tput = sdf(best_pos) is bit-identical to the scan's running min cm
        // (same weight values, identical position arithmetic), so only the
        // running min is tracked and the final eval is eliminated.
        const float step = (1.0f + 1.0f / 64.0f) / 64.0f;  // 65/4096, exact fp32
        float cm = sdf_eval(&s, rox, roy, roz);
        #pragma unroll 1
        for (int i = 1; i <= 64; ++i) {
            asm volatile("" ::: "memory");   // block cross-iteration hoist/CSE
            float t = step * (float)i;
            float sd = sdf_eval(&s, fmaf(rdx, t, rox), fmaf(rdy, t, roy), fmaf(rdz, t, roz));
            cm = fminf(cm, sd);
        }
        out[4 * ray + 3] = cm;
    }
}

extern "C" void kernel_launch(void* const* d_in, const int* in_sizes, int n_in,
                              void* d_out, int out_size) {
    sdf_march_kernel<<<2 * NBLK, THREADS>>>(
        (const float*)d_in[0],
        (const float*)d_in[1], (const float*)d_in[2],
        (const float*)d_in[3], (const float*)d_in[4],
        (const float*)d_in[5], (const float*)d_in[6],
        (const float*)d_in[7], (const float*)d_in[8],
        (const float*)d_in[9], (const float*)d_in[10],
        (float*)d_out);
}

// round 10
// speedup vs baseline: 3.2868x; 1.5855x over previous
#include <cuda_runtime.h>

typedef unsigned long long u64;

#define NRAYS 32768
#define THREADS 128
#define RAYS_PER_BLOCK (THREADS * 2)            // 2 rays per thread
#define NBLK (NRAYS / RAYS_PER_BLOCK)           // 128 march blocks + 128 scan blocks

// ---- packed f32x2 helpers (Blackwell sm_103a) ----
__device__ __forceinline__ u64 pack2(float a, float b) {
    u64 r; asm("mov.b64 %0, {%1, %2};" : "=l"(r) : "f"(a), "f"(b)); return r;
}
__device__ __forceinline__ float2 unpack2(u64 v) {
    float2 r; asm("mov.b64 {%0, %1}, %2;" : "=f"(r.x), "=f"(r.y) : "l"(v)); return r;
}
__device__ __forceinline__ u64 ffma2(u64 a, u64 b, u64 c) {
    u64 d; asm("fma.rn.f32x2 %0, %1, %2, %3;" : "=l"(d) : "l"(a), "l"(b), "l"(c)); return d;
}
__device__ __forceinline__ u64 fadd2(u64 a, u64 b) {
    u64 d; asm("add.rn.f32x2 %0, %1, %2;" : "=l"(d) : "l"(a), "l"(b)); return d;
}
__device__ __forceinline__ u64 relu2(u64 v) {
    float2 f = unpack2(v);
    return pack2(fmaxf(f.x, 0.0f), fmaxf(f.y, 0.0f));
}
__device__ __forceinline__ u64 splat2(float x) { return pack2(x, x); }

struct __align__(16) Weights {
    float W0[3 * 64];
    float b0[64];
    float W1[64 * 64];
    float b1[64];
    float W2[64];
    float b2;
    float pad[3];
    float Wr0[6 * 64];
    float br0[64];
    float Wr1[64 * 3];
    float br1[3];
};

// Two-point SDF eval: every shared-memory weight load feeds FOUR ffma2
// (2 neurons x 2 rays), halving L1tex traffic per MAC (R6 profile: L1=81%,
// LDS-bound). Layer1 quarter-tile loop is kept as a DYNAMIC loop
// (#pragma unroll 1) so the function body stays small (~10KB SASS): the
// inner k-loop is still fully unrolled with static register indexing.
// __noinline__ is load-bearing (fences LICM of weight loads out of the
// march/scan loops, which previously spilled ~10KB/thread).
__device__ __noinline__ float2 sdf_eval2(const Weights* __restrict__ sp,
                                         float pxA, float pyA, float pzA,
                                         float pxB, float pyB, float pzB) {
    const Weights& s = *sp;
    u64 hA[32], hB[32];
    {
        const float4* b4 = (const float4*)s.b0;
        #pragma unroll
        for (int q = 0; q < 16; q++) {
            float4 v = b4[q];
            u64 lo = pack2(v.x, v.y), hi = pack2(v.z, v.w);
            hA[2 * q] = lo; hA[2 * q + 1] = hi;
            hB[2 * q] = lo; hB[2 * q + 1] = hi;
        }
        float pa[3] = {pxA, pyA, pzA};
        float pb[3] = {pxB, pyB, pzB};
        #pragma unroll
        for (int i = 0; i < 3; i++) {
            u64 xA = splat2(pa[i]);
            u64 xB = splat2(pb[i]);
            const float4* w = (const float4*)(s.W0 + i * 64);
            #pragma unroll
            for (int q = 0; q < 16; q++) {
                float4 wv = w[q];
                u64 wlo = pack2(wv.x, wv.y), whi = pack2(wv.z, wv.w);
                hA[2 * q]     = ffma2(xA, wlo, hA[2 * q]);
                hA[2 * q + 1] = ffma2(xA, whi, hA[2 * q + 1]);
                hB[2 * q]     = ffma2(xB, wlo, hB[2 * q]);
                hB[2 * q + 1] = ffma2(xB, whi, hB[2 * q + 1]);
            }
        }
        #pragma unroll
        for (int q = 0; q < 32; q++) { hA[q] = relu2(hA[q]); hB[q] = relu2(hB[q]); }
    }

    u64 dA0 = 0ull, dA1 = 0ull, dB0 = 0ull, dB1 = 0ull;
    #pragma unroll 1
    for (int qt = 0; qt < 4; qt++) {
        u64 accA[8], accB[8];
        {
            const float4* b4 = (const float4*)(s.b1 + qt * 16);
            #pragma unroll
            for (int q = 0; q < 4; q++) {
                float4 v = b4[q];
                u64 lo = pack2(v.x, v.y), hi = pack2(v.z, v.w);
                accA[2 * q] = lo; accA[2 * q + 1] = hi;
                accB[2 * q] = lo; accB[2 * q + 1] = hi;
            }
        }
        const float4* wbase = (const float4*)(s.W1 + qt * 16);
        #pragma unroll
        for (int kk = 0; kk < 32; kk++) {
            float2 hpA = unpack2(hA[kk]);
            float2 hpB = unpack2(hB[kk]);
            {
                u64 xA = splat2(hpA.x), xB = splat2(hpB.x);
                const float4* w = wbase + (2 * kk) * 16;
                #pragma unroll
                for (int q = 0; q < 4; q++) {
                    float4 wv = w[q];
                    u64 wlo = pack2(wv.x, wv.y), whi = pack2(wv.z, wv.w);
                    accA[2 * q]     = ffma2(xA, wlo, accA[2 * q]);
                    accA[2 * q + 1] = ffma2(xA, whi, accA[2 * q + 1]);
                    accB[2 * q]     = ffma2(xB, wlo, accB[2 * q]);
                    accB[2 * q + 1] = ffma2(xB, whi, accB[2 * q + 1]);
                }
            }
            {
                u64 xA = splat2(hpA.y), xB = splat2(hpB.y);
                const float4* w = wbase + (2 * kk + 1) * 16;
                #pragma unroll
                for (int q = 0; q < 4; q++) {
                    float4 wv = w[q];
                    u64 wlo = pack2(wv.x, wv.y), whi = pack2(wv.z, wv.w);
                    accA[2 * q]     = ffma2(xA, wlo, accA[2 * q]);
                    accA[2 * q + 1] = ffma2(xA, whi, accA[2 * q + 1]);
                    accB[2 * q]     = ffma2(xB, wlo, accB[2 * q]);
                    accB[2 * q + 1] = ffma2(xB, whi, accB[2 * q + 1]);
                }
            }
        }
        // layer 2 (fused): relu then dot with W2 quarter
        const float4* w2 = (const float4*)(s.W2 + qt * 16);
        #pragma unroll
        for (int q = 0; q < 4; q++) {
            float4 wv = w2[q];
            u64 wlo = pack2(wv.x, wv.y), whi = pack2(wv.z, wv.w);
            dA0 = ffma2(relu2(accA[2 * q]),     wlo, dA0);
            dA1 = ffma2(relu2(accA[2 * q + 1]), whi, dA1);
            dB0 = ffma2(relu2(accB[2 * q]),     wlo, dB0);
            dB1 = ffma2(relu2(accB[2 * q + 1]), whi, dB1);
        }
    }
    float2 fa = unpack2(fadd2(dA0, dA1));
    float2 fb = unpack2(fadd2(dB0, dB1));
    return make_float2(fa.x + fa.y + s.b2, fb.x + fb.y + s.b2);
}

// Reflectance MLP: sigmoid(relu([p,d]@Wr0+br0)@Wr1+br1). Called once.
__device__ __noinline__ void refl_eval(const Weights* __restrict__ sp,
                                       const float* in6, float* rgb) {
    const Weights& s = *sp;
    u64 h[32];
    {
        const float4* b4 = (const float4*)s.br0;
        #pragma unroll
        for (int q = 0; q < 16; q++) {
            float4 v = b4[q];
            h[2 * q]     = pack2(v.x, v.y);
            h[2 * q + 1] = pack2(v.z, v.w);
        }
        #pragma unroll
        for (int i = 0; i < 6; i++) {
            u64 xi = splat2(in6[i]);
            const float4* w = (const float4*)(s.Wr0 + i * 64);
            #pragma unroll
            for (int q = 0; q < 16; q++) {
                float4 wv = w[q];
                h[2 * q]     = ffma2(xi, pack2(wv.x, wv.y), h[2 * q]);
                h[2 * q + 1] = ffma2(xi, pack2(wv.z, wv.w), h[2 * q + 1]);
            }
        }
    }
    float a0 = s.br1[0], a1 = s.br1[1], a2 = s.br1[2];
    #pragma unroll
    for (int kk = 0; kk < 32; kk++) {
        float2 hp = unpack2(h[kk]);
        float v0 = fmaxf(hp.x, 0.0f);
        float v1 = fmaxf(hp.y, 0.0f);
        const float* w = s.Wr1 + (2 * kk) * 3;
        a0 = fmaf(v0, w[0], a0);
        a1 = fmaf(v0, w[1], a1);
        a2 = fmaf(v0, w[2], a2);
        a0 = fmaf(v1, w[3], a0);
        a1 = fmaf(v1, w[4], a1);
        a2 = fmaf(v1, w[5], a2);
    }
    rgb[0] = 1.0f / (1.0f + expf(-a0));
    rgb[1] = 1.0f / (1.0f + expf(-a1));
    rgb[2] = 1.0f / (1.0f + expf(-a2));
}

// Grid = 2*NBLK. Blocks [0,NBLK): march+reflectance for 2 rays/thread.
// Blocks [NBLK,2*NBLK): tput argmin scan for 2 rays/thread. Tasks are
// independent (scan uses identical weight values via stop_gradient) and
// write disjoint components of each output row.
__global__ void __launch_bounds__(THREADS) sdf_march_kernel(
    const float* __restrict__ rays,
    const float* __restrict__ gW0, const float* __restrict__ gb0,
    const float* __restrict__ gW1, const float* __restrict__ gb1,
    const float* __restrict__ gW2, const float* __restrict__ gb2,
    const float* __restrict__ gWr0, const float* __restrict__ gbr0,
    const float* __restrict__ gWr1, const float* __restrict__ gbr1,
    float* __restrict__ out)
{
    __shared__ Weights s;
    int tid = threadIdx.x;
    for (int i = tid; i < 3 * 64; i += THREADS) s.W0[i] = gW0[i];
    for (int i = tid; i < 64; i += THREADS) s.b0[i] = gb0[i];
    for (int i = tid; i < 64 * 64; i += THREADS) s.W1[i] = gW1[i];
    for (int i = tid; i < 64; i += THREADS) s.b1[i] = gb1[i];
    for (int i = tid; i < 64; i += THREADS) s.W2[i] = gW2[i];
    if (tid == 0) s.b2 = gb2[0];
    for (int i = tid; i < 6 * 64; i += THREADS) s.Wr0[i] = gWr0[i];
    for (int i = tid; i < 64; i += THREADS) s.br0[i] = gbr0[i];
    for (int i = tid; i < 64 * 3; i += THREADS) s.Wr1[i] = gWr1[i];
    for (int i = tid; i < 3; i += THREADS) s.br1[i] = gbr1[i];
    __syncthreads();

    bool is_scan = blockIdx.x >= NBLK;
    int blk = blockIdx.x - (is_scan ? NBLK : 0);
    int rayA = (blk * THREADS + tid) * 2;
    int rayB = rayA + 1;
    const float* ra = rays + rayA * 6;
    const float* rb = rays + rayB * 6;
    float roxA = ra[0], royA = ra[1], rozA = ra[2];
    float rdxA = ra[3], rdyA = ra[4], rdzA = ra[5];
    float roxB = rb[0], royB = rb[1], rozB = rb[2];
    float rdxB = rb[3], rdyB = rb[4], rdzB = rb[5];

    if (!is_scan) {
        // ---- sphere march (hit lanes freeze cd -> all-hit break is exact) ----
        float cdA = 0.0f, cdB = 0.0f;
        bool hitA = false, hitB = false;
        #pragma unroll 1
        for (int it = 0; it < 64; ++it) {
            asm volatile("" ::: "memory");   // block cross-iteration hoist/CSE
            float2 d = sdf_eval2(&s,
                fmaf(rdxA, cdA, roxA), fmaf(rdyA, cdA, royA), fmaf(rdzA, cdA, rozA),
                fmaf(rdxB, cdB, roxB), fmaf(rdyB, cdB, royB), fmaf(rdzB, cdB, rozB));
            bool hA = (d.x < 1e-4f) && (cdA >= 0.0f) && (cdA <= 1.0f);
            bool hB = (d.y < 1e-4f) && (cdB >= 0.0f) && (cdB <= 1.0f);
            hitA = hitA || hA;
            hitB = hitB || hB;
            if (!hitA) cdA += d.x;
            if (!hitB) cdB += d.y;
            if (__all_sync(0xffffffffu, hitA && hitB)) break;
        }

        // ---- reflectance (skipped entirely for all-miss warps) ----
        float rgbA[3] = {0.0f, 0.0f, 0.0f};
        float rgbB[3] = {0.0f, 0.0f, 0.0f};
        if (__any_sync(0xffffffffu, hitA || hitB)) {
            float in6A[6] = { fmaf(rdxA, cdA, roxA), fmaf(rdyA, cdA, royA),
                              fmaf(rdzA, cdA, rozA), rdxA, rdyA, rdzA };
            refl_eval(&s, in6A, rgbA);
            float in6B[6] = { fmaf(rdxB, cdB, roxB), fmaf(rdyB, cdB, royB),
                              fmaf(rdzB, cdB, rozB), rdxB, rdyB, rdzB };
            refl_eval(&s, in6B, rgbB);
            if (!hitA) { rgbA[0] = 0.0f; rgbA[1] = 0.0f; rgbA[2] = 0.0f; }
            if (!hitB) { rgbB[0] = 0.0f; rgbB[1] = 0.0f; rgbB[2] = 0.0f; }
        }
        out[4 * rayA + 0] = rgbA[0];
        out[4 * rayA + 1] = rgbA[1];
        out[4 * rayA + 2] = rgbA[2];
        out[4 * rayB + 0] = rgbB[0];
        out[4 * rayB + 1] = rgbB[1];
        out[4 * rayB + 2] = rgbB[2];
    } else {
        // ---- throughput argmin scan: t = step*i, i = 0..64 ----
        // tput = sdf(best_pos) equals the scan's running min (same weight
        // values, identical position arithmetic), so only the min is tracked.
        const float step = (1.0f + 1.0f / 64.0f) / 64.0f;  // 65/4096, exact fp32
        float2 cm = sdf_eval2(&s, roxA, royA, rozA, roxB, royB, rozB);
        #pragma unroll 1
        for (int i = 1; i <= 64; ++i) {
            asm volatile("" ::: "memory");   // block cross-iteration hoist/CSE
            float t = step * (float)i;
            float2 sd = sdf_eval2(&s,
                fmaf(rdxA, t, roxA), fmaf(rdyA, t, royA), fmaf(rdzA, t, rozA),
                fmaf(rdxB, t, roxB), fmaf(rdyB, t, royB), fmaf(rdzB, t, rozB));
            cm.x = fminf(cm.x, sd.x);
            cm.y = fminf(cm.y, sd.y);
        }
        out[4 * rayA + 3] = cm.x;
        out[4 * rayB + 3] = cm.y;
    }
}

extern "C" void kernel_launch(void* const* d_in, const int* in_sizes, int n_in,
                              void* d_out, int out_size) {
    sdf_march_kernel<<<2 * NBLK, THREADS>>>(
        (const float*)d_in[0],
        (const float*)d_in[1], (const float*)d_in[2],
        (const float*)d_in[3], (const float*)d_in[4],
        (const float*)d_in[5], (const float*)d_in[6],
        (const float*)d_in[7], (const float*)d_in[8],
        (const float*)d_in[9], (const float*)d_in[10],
        (float*)d_out);
}